// round 13
// baseline (speedup 1.0000x reference)
#include <cuda_runtime.h>
#include <cuda_fp16.h>
#include <cstdint>

#define NN 4096
#define BB 8
#define NBTOT (BB*NN)
#define LSC 2048.0f
#define ILSC (1.0f/2048.0f)
typedef __half hf;

__device__ __forceinline__ uint32_t pk2(float a, float b) {
    __half2 h = __floats2half2_rn(a, b);
    return *(uint32_t*)&h;
}
__device__ __forceinline__ void mma16(float* d, const uint32_t* a, uint32_t b0, uint32_t b1) {
    asm volatile("mma.sync.aligned.m16n8k16.row.col.f32.f16.f16.f32 "
        "{%0,%1,%2,%3}, {%4,%5,%6,%7}, {%8,%9}, {%0,%1,%2,%3};"
        : "+f"(d[0]), "+f"(d[1]), "+f"(d[2]), "+f"(d[3])
        : "r"(a[0]), "r"(a[1]), "r"(a[2]), "r"(a[3]), "r"(b0), "r"(b1));
}
__device__ __forceinline__ void ldfA(uint32_t* f, const hf* base, int S, int rb, int kb, int r, int q2) {
    f[0] = *(const uint32_t*)(base + (rb + r) * S + kb + q2);
    f[1] = *(const uint32_t*)(base + (rb + r + 8) * S + kb + q2);
    f[2] = *(const uint32_t*)(base + (rb + r) * S + kb + q2 + 8);
    f[3] = *(const uint32_t*)(base + (rb + r + 8) * S + kb + q2 + 8);
}
__device__ __forceinline__ void cpa16(const void* s, const void* g) {
    uint32_t a = (uint32_t)__cvta_generic_to_shared(s);
    asm volatile("cp.async.ca.shared.global [%0], [%1], 16;" :: "r"(a), "l"(g) : "memory");
}
#define CPA_COMMIT() asm volatile("cp.async.commit_group;" ::: "memory")
#define CPA_WAIT()   asm volatile("cp.async.wait_group 0;" ::: "memory")

template<int C, int ROWS, int S>
__device__ __forceinline__ void cpa_tile(hf* sh, hf* sl, const hf* gh, const hf* gl, size_t base, int t) {
    constexpr int OPS = ROWS * C / 8;
    #pragma unroll
    for (int i = 0; i < (OPS + 255) / 256; i++) {
        int idx = t + i * 256;
        if ((OPS & 255) == 0 || idx < OPS) {
            int row = idx / (C / 8), cu = idx % (C / 8);
            size_t go = base + (size_t)row * C + cu * 8;
            cpa16(sh + row * S + cu * 8, gh + go);
            cpa16(sl + row * S + cu * 8, gl + go);
        }
    }
}
template<int C, int SE>
__device__ __forceinline__ void cpa_vtile(hf* sh, hf* sl, const hf* gh, const hf* gl,
                                          size_t bC, int n0, int t) {
    constexpr int OPS = C * 8;
    #pragma unroll
    for (int i = 0; i < (OPS + 255) / 256; i++) {
        int idx = t + i * 256;
        if ((OPS & 255) == 0 || idx < OPS) {
            int row = idx >> 3, cu = idx & 7;
            size_t go = (bC + row) * NN + n0 + cu * 8;
            cpa16(sh + row * SE + cu * 8, gh + go);
            cpa16(sl + row * SE + cu * 8, gl + go);
        }
    }
}

#define BUF 2097152
__device__ float SCR[8*BUF + 2*BB*NN + 256 + 5*128 + 1024];

__device__ __forceinline__ void bn_coef8(const float* __restrict__ st2, const float* __restrict__ g,
                                         const float* __restrict__ be, int c, float& sc, float& sh) {
    float S = 0.f, Q = 0.f;
    #pragma unroll
    for (int b = 0; b < BB; b++) { S += st2[b * 128 + c]; Q += st2[b * 128 + 64 + c]; }
    const float inv = 1.0f / (float)NBTOT;
    float mean = S * inv;
    float var = Q * inv - mean * mean;
    float r = rsqrtf(var + 1e-5f);
    sc = g[c] * r; sh = be[c] - sc * mean;
}

__global__ void k_stats1(const float* __restrict__ d, int C, float* __restrict__ st2) {
    int c = blockIdx.x, b = blockIdx.y;
    const float* p = d + (b * C + c) * NN;
    float s = 0.f, sq = 0.f;
    for (int i = threadIdx.x; i < NN; i += 256) { float v = p[i]; s += v; sq += v * v; }
    __shared__ float shs[8], shq[8];
    for (int o = 16; o; o >>= 1) { s += __shfl_down_sync(~0u, s, o); sq += __shfl_down_sync(~0u, sq, o); }
    if ((threadIdx.x & 31) == 0) { shs[threadIdx.x >> 5] = s; shq[threadIdx.x >> 5] = sq; }
    __syncthreads();
    if (threadIdx.x == 0) {
        float S = 0.f, Q = 0.f;
        #pragma unroll
        for (int i = 0; i < 8; i++) { S += shs[i]; Q += shq[i]; }
        st2[b * 128 + c] = S; st2[b * 128 + 64 + c] = Q;
    }
}

__global__ void k_conv1(const float* __restrict__ x, const float* __restrict__ w,
                        const float* __restrict__ bias, float* __restrict__ y) {
    __shared__ float ws[192], bs[32];
    int t = threadIdx.x;
    if (t < 192) ws[t] = w[t];
    if (t < 32) bs[t] = bias[t];
    __syncthreads();
    int b = blockIdx.y, n = blockIdx.x * 256 + t;
    float in[6];
    #pragma unroll
    for (int c = 0; c < 6; c++) in[c] = x[(b * 6 + c) * NN + n];
    #pragma unroll
    for (int o = 0; o < 32; o++) {
        float a = bs[o];
        #pragma unroll
        for (int c = 0; c < 6; c++) a = fmaf(ws[o * 6 + c], in[c], a);
        y[(b * 32 + o) * NN + n] = a;
    }
}

__global__ void k_bnconv32(const float* __restrict__ yin, const float* __restrict__ st2,
                           const float* __restrict__ g, const float* __restrict__ be,
                           const float* __restrict__ w, const float* __restrict__ bias,
                           float* __restrict__ yout) {
    __shared__ float ws[1024], bs[32], sc[32], sh[32];
    int t = threadIdx.x;
    for (int i = t; i < 1024; i += 256) ws[i] = w[i];
    if (t < 32) { bs[t] = bias[t]; bn_coef8(st2, g, be, t, sc[t], sh[t]); }
    __syncthreads();
    int b = blockIdx.y, n = blockIdx.x * 256 + t;
    float in[32];
    #pragma unroll
    for (int c = 0; c < 32; c++) in[c] = fmaxf(fmaf(sc[c], yin[(b * 32 + c) * NN + n], sh[c]), 0.f);
    for (int o = 0; o < 32; o++) {
        float a = bs[o];
        #pragma unroll
        for (int c = 0; c < 32; c++) a = fmaf(ws[o * 32 + c], in[c], a);
        yout[(b * 32 + o) * NN + n] = a;
    }
}

template<int C>
__global__ void k_bnqkv(const float* __restrict__ yin, const float* __restrict__ st2,
                        const float* __restrict__ g, const float* __restrict__ be,
                        const float* __restrict__ wqk, const float* __restrict__ wv,
                        const float* __restrict__ bv, float* __restrict__ h,
                        hf* __restrict__ qh, hf* __restrict__ ql,
                        hf* __restrict__ vh, hf* __restrict__ vl) {
    __shared__ float wq_s[C*C], wv_s[C*C], bvs[C], sc[C], sh[C];
    int t = threadIdx.x;
    for (int i = t; i < C*C; i += 256) { wq_s[i] = wqk[i]; wv_s[i] = wv[i]; }
    if (t < C) { bvs[t] = bv[t]; bn_coef8(st2, g, be, t, sc[t], sh[t]); }
    __syncthreads();
    int b = blockIdx.y, n = blockIdx.x * 256 + t;
    float in[C];
    #pragma unroll
    for (int c = 0; c < C; c++) {
        float val = fmaxf(fmaf(sc[c], yin[(b * C + c) * NN + n], sh[c]), 0.f);
        in[c] = val;
        h[(b * C + c) * NN + n] = val;
    }
    size_t qoff = ((size_t)b * NN + n) * C;
    for (int og = 0; og < C; og += 4) {
        uint32_t uh[2], ul[2];
        #pragma unroll
        for (int oo = 0; oo < 4; oo += 2) {
            float q0 = 0.f, q1 = 0.f, av0 = bvs[og+oo], av1 = bvs[og+oo+1];
            #pragma unroll
            for (int c = 0; c < C; c++) {
                q0 = fmaf(wq_s[(og+oo) * C + c], in[c], q0);
                q1 = fmaf(wq_s[(og+oo+1) * C + c], in[c], q1);
                av0 = fmaf(wv_s[(og+oo) * C + c], in[c], av0);
                av1 = fmaf(wv_s[(og+oo+1) * C + c], in[c], av1);
            }
            hf h0 = __float2half_rn(q0), h1 = __float2half_rn(q1);
            uh[oo>>1] = ((uint32_t)__half_as_ushort(h1) << 16) | __half_as_ushort(h0);
            ul[oo>>1] = pk2((q0 - __half2float(h0)) * LSC, (q1 - __half2float(h1)) * LSC);
            hf v0 = __float2half_rn(av0), v1 = __float2half_rn(av1);
            vh[(b * C + og+oo) * NN + n] = v0;
            vh[(b * C + og+oo+1) * NN + n] = v1;
            vl[(b * C + og+oo) * NN + n] = __float2half_rn((av0 - __half2float(v0)) * LSC);
            vl[(b * C + og+oo+1) * NN + n] = __float2half_rn((av1 - __half2float(v1)) * LSC);
        }
        *(uint2*)(qh + qoff + og) = make_uint2(uh[0], uh[1]);
        *(uint2*)(ql + qoff + og) = make_uint2(ul[0], ul[1]);
    }
}

// ---- pass A: 64 n-rows/block, cp.async double-buffered B tiles, 2 blocks/SM ----
template<int C>
__global__ void __launch_bounds__(256, 2) k_gramA(const hf* __restrict__ qh, const hf* __restrict__ ql,
                                                  float* __restrict__ Mr, float* __restrict__ iLv) {
    constexpr int S = C + 8;
    extern __shared__ float smf[];
    float *RM = smf, *RL = smf + 256;
    hf* Ah = (hf*)(smf + 512);
    hf* Al = Ah + 64 * S;
    hf* Bbase = Al + 64 * S;              // dbuf: each 256*S (h 128*S + l 128*S)
    const int t = threadIdx.x, w = t >> 5, lane = t & 31;
    const int b = blockIdx.y, n0 = blockIdx.x * 64;
    const int rw = (w >> 2) * 32, cw = (w & 3) * 32;
    const int r = lane >> 2, q2 = (lane & 3) * 2;
    const size_t bN = (size_t)b * NN;
    cpa_tile<C, 64, S>(Ah, Al, qh, ql, (bN + n0) * C, t);
    CPA_COMMIT();
    cpa_tile<C, 128, S>(Bbase, Bbase + 128 * S, qh, ql, bN * C, t);
    CPA_COMMIT();
    float Mv[4], Lv[4];
    #pragma unroll
    for (int i = 0; i < 4; i++) { Mv[i] = -1e30f; Lv[i] = 0.f; }
    for (int mt = 0; mt < 32; mt++) {
        CPA_WAIT();
        __syncthreads();
        hf* Bh = Bbase + (mt & 1) * 256 * S;
        hf* Bl = Bh + 128 * S;
        if (mt + 1 < 32) {
            hf* Bn = Bbase + ((mt + 1) & 1) * 256 * S;
            cpa_tile<C, 128, S>(Bn, Bn + 128 * S, qh, ql, (bN + (mt + 1) * 128) * C, t);
            CPA_COMMIT();
        }
        float accH[2][4][4], accX[2][4][4];
        #pragma unroll
        for (int rf = 0; rf < 2; rf++)
            #pragma unroll
            for (int j = 0; j < 4; j++)
                #pragma unroll
                for (int e = 0; e < 4; e++) { accH[rf][j][e] = 0.f; accX[rf][j][e] = 0.f; }
        #pragma unroll
        for (int ks = 0; ks < C / 16; ks++) {
            int kb = ks * 16;
            uint32_t ah[2][4], al[2][4];
            #pragma unroll
            for (int rf = 0; rf < 2; rf++) {
                ldfA(ah[rf], Ah, S, rw + rf * 16, kb, r, q2);
                ldfA(al[rf], Al, S, rw + rf * 16, kb, r, q2);
            }
            #pragma unroll
            for (int j = 0; j < 4; j++) {
                int cb = cw + j * 8;
                uint32_t bh0 = *(const uint32_t*)(Bh + (cb + r) * S + kb + q2);
                uint32_t bh1 = *(const uint32_t*)(Bh + (cb + r) * S + kb + q2 + 8);
                uint32_t bl0 = *(const uint32_t*)(Bl + (cb + r) * S + kb + q2);
                uint32_t bl1 = *(const uint32_t*)(Bl + (cb + r) * S + kb + q2 + 8);
                #pragma unroll
                for (int rf = 0; rf < 2; rf++) {
                    mma16(accH[rf][j], ah[rf], bh0, bh1);
                    mma16(accX[rf][j], ah[rf], bl0, bl1);
                    mma16(accX[rf][j], al[rf], bh0, bh1);
                }
            }
        }
        #pragma unroll
        for (int rf = 0; rf < 2; rf++)
            #pragma unroll
            for (int h = 0; h < 2; h++) {
                int i = rf * 2 + h;
                float sv[8];
                #pragma unroll
                for (int j = 0; j < 4; j++) {
                    sv[2*j]   = fmaf(accX[rf][j][2*h],   ILSC, accH[rf][j][2*h]);
                    sv[2*j+1] = fmaf(accX[rf][j][2*h+1], ILSC, accH[rf][j][2*h+1]);
                }
                float tm = -1e30f;
                #pragma unroll
                for (int j = 0; j < 8; j++) tm = fmaxf(tm, sv[j]);
                float Mn = fmaxf(Mv[i], tm);
                float l = Lv[i] * __expf(Mv[i] - Mn);
                #pragma unroll
                for (int j = 0; j < 8; j++) l += __expf(sv[j] - Mn);
                Mv[i] = Mn; Lv[i] = l;
            }
    }
    #pragma unroll
    for (int i = 0; i < 4; i++)
        #pragma unroll
        for (int o = 1; o <= 2; o <<= 1) {
            float M2 = __shfl_xor_sync(~0u, Mv[i], o);
            float L2 = __shfl_xor_sync(~0u, Lv[i], o);
            float Mn = fmaxf(Mv[i], M2);
            Lv[i] = Lv[i] * __expf(Mv[i] - Mn) + L2 * __expf(M2 - Mn);
            Mv[i] = Mn;
        }
    __syncthreads();
    if ((lane & 3) == 0) {
        #pragma unroll
        for (int i = 0; i < 4; i++) {
            int row = rw + (i >> 1) * 16 + (i & 1) * 8 + r;
            RM[row * 4 + (w & 3)] = Mv[i];
            RL[row * 4 + (w & 3)] = Lv[i];
        }
    }
    __syncthreads();
    if (t < 64) {
        float M = -1e30f, L = 0.f;
        #pragma unroll
        for (int p = 0; p < 4; p++) {
            float m2 = RM[t * 4 + p], l2 = RL[t * 4 + p];
            float Mn = fmaxf(M, m2);
            L = L * __expf(M - Mn) + l2 * __expf(m2 - Mn);
            M = Mn;
        }
        Mr[b * NN + n0 + t] = M;
        iLv[b * NN + n0 + t] = 1.0f / L;
    }
}

// ---- pass B: 64 m-rows/block, cp.async dbuf Qn/V/M/L, 2 blocks/SM ----
template<int C>
__global__ void __launch_bounds__(256, 2) k_gramB(const hf* __restrict__ qh, const hf* __restrict__ ql,
                                                  const hf* __restrict__ vhp, const hf* __restrict__ vlp,
                                                  const float* __restrict__ Mr, const float* __restrict__ iLv,
                                                  float* __restrict__ xrT) {
    constexpr int S = C + 8, SE = 72, NJ2 = C / 16;
    extern __shared__ float smf[];
    float *MshB = smf;          // [2][64]
    float *LshB = smf + 128;    // [2][64]
    float *Red  = smf + 256;    // 128
    float *Sinv = smf + 384;    // 64
    hf* Qmh = (hf*)(smf + 512);
    hf* Qml = Qmh + 64 * S;
    hf* Qbase = Qml + 64 * S;            // dbuf: each 128*S
    hf* Vbase = Qbase + 2 * 128 * S;     // dbuf: each 2*C*SE
    hf* Eh = Vbase + 2 * 2 * C * SE;
    hf* El = Eh + 64 * SE;
    const int t = threadIdx.x, w = t >> 5, lane = t & 31;
    const int b = blockIdx.y, m0 = blockIdx.x * 64;
    const int rw = (w >> 1) * 16, cw = (w & 1) * 32, cw2 = (w & 1) * (C / 2);
    const int r = lane >> 2, q2 = (lane & 3) * 2;
    const size_t bN = (size_t)b * NN, bC = (size_t)b * C;
    cpa_tile<C, 64, S>(Qmh, Qml, qh, ql, (bN + m0) * C, t);
    CPA_COMMIT();
    cpa_tile<C, 64, S>(Qbase, Qbase + 64 * S, qh, ql, bN * C, t);
    cpa_vtile<C, SE>(Vbase, Vbase + C * SE, vhp, vlp, bC, 0, t);
    if (t < 16) cpa16(MshB + t * 4, Mr + bN + t * 4);
    else if (t < 32) cpa16(LshB + (t - 16) * 4, iLv + bN + (t - 16) * 4);
    CPA_COMMIT();
    float acc2H[NJ2][4], acc2X[NJ2][4];
    #pragma unroll
    for (int j = 0; j < NJ2; j++)
        #pragma unroll
        for (int e = 0; e < 4; e++) { acc2H[j][e] = 0.f; acc2X[j][e] = 0.f; }
    float sacc[2] = {0.f, 0.f};
    for (int nt = 0; nt < 64; nt++) {
        CPA_WAIT();
        __syncthreads();
        int bi = nt & 1;
        hf* Qnh = Qbase + bi * 128 * S;
        hf* Qnl = Qnh + 64 * S;
        hf* Vh = Vbase + bi * 2 * C * SE;
        hf* Vl = Vh + C * SE;
        const float* Msh = MshB + bi * 64;
        const float* Lsh = LshB + bi * 64;
        if (nt + 1 < 64) {
            int bj = (nt + 1) & 1, n1 = (nt + 1) * 64;
            hf* Qn2 = Qbase + bj * 128 * S;
            hf* V2 = Vbase + bj * 2 * C * SE;
            cpa_tile<C, 64, S>(Qn2, Qn2 + 64 * S, qh, ql, (bN + n1) * C, t);
            cpa_vtile<C, SE>(V2, V2 + C * SE, vhp, vlp, bC, n1, t);
            if (t < 16) cpa16(MshB + bj * 64 + t * 4, Mr + bN + n1 + t * 4);
            else if (t < 32) cpa16(LshB + bj * 64 + (t - 16) * 4, iLv + bN + n1 + (t - 16) * 4);
            CPA_COMMIT();
        }
        float accS[4][4], accSX[4][4];
        #pragma unroll
        for (int j = 0; j < 4; j++)
            #pragma unroll
            for (int e = 0; e < 4; e++) { accS[j][e] = 0.f; accSX[j][e] = 0.f; }
        #pragma unroll
        for (int ks = 0; ks < C / 16; ks++) {
            int kb = ks * 16;
            uint32_t ah[4], al[4];
            ldfA(ah, Qmh, S, rw, kb, r, q2);
            ldfA(al, Qml, S, rw, kb, r, q2);
            #pragma unroll
            for (int j = 0; j < 4; j++) {
                int cb = cw + j * 8;
                uint32_t bh0 = *(const uint32_t*)(Qnh + (cb + r) * S + kb + q2);
                uint32_t bh1 = *(const uint32_t*)(Qnh + (cb + r) * S + kb + q2 + 8);
                uint32_t bl0 = *(const uint32_t*)(Qnl + (cb + r) * S + kb + q2);
                uint32_t bl1 = *(const uint32_t*)(Qnl + (cb + r) * S + kb + q2 + 8);
                mma16(accS[j], ah, bh0, bh1);
                mma16(accSX[j], ah, bl0, bl1);
                mma16(accSX[j], al, bh0, bh1);
            }
        }
        #pragma unroll
        for (int h = 0; h < 2; h++) {
            int row = rw + h * 8 + r;
            #pragma unroll
            for (int j = 0; j < 4; j++) {
                int col = cw + j * 8 + q2;
                float s0 = fmaf(accSX[j][2*h],   ILSC, accS[j][2*h]);
                float s1 = fmaf(accSX[j][2*h+1], ILSC, accS[j][2*h+1]);
                float e0 = __expf(s0 - Msh[col])     * Lsh[col];
                float e1 = __expf(s1 - Msh[col + 1]) * Lsh[col + 1];
                sacc[h] += e0 + e1;
                hf eh0 = __float2half_rn(e0), eh1 = __float2half_rn(e1);
                *(uint32_t*)(Eh + row * SE + col) =
                    ((uint32_t)__half_as_ushort(eh1) << 16) | __half_as_ushort(eh0);
                *(uint32_t*)(El + row * SE + col) =
                    pk2((e0 - __half2float(eh0)) * LSC, (e1 - __half2float(eh1)) * LSC);
            }
        }
        __syncthreads();
        #pragma unroll
        for (int ks = 0; ks < 4; ks++) {
            int kb = ks * 16;
            uint32_t ef[4], efl[4];
            ldfA(ef, Eh, SE, rw, kb, r, q2);
            ldfA(efl, El, SE, rw, kb, r, q2);
            #pragma unroll
            for (int j = 0; j < NJ2; j++) {
                int cc = cw2 + j * 8;
                uint32_t bh0 = *(const uint32_t*)(Vh + (cc + r) * SE + kb + q2);
                uint32_t bh1 = *(const uint32_t*)(Vh + (cc + r) * SE + kb + q2 + 8);
                uint32_t bl0 = *(const uint32_t*)(Vl + (cc + r) * SE + kb + q2);
                uint32_t bl1 = *(const uint32_t*)(Vl + (cc + r) * SE + kb + q2 + 8);
                mma16(acc2H[j], ef, bh0, bh1);
                mma16(acc2X[j], ef, bl0, bl1);
                mma16(acc2X[j], efl, bh0, bh1);
            }
        }
    }
    #pragma unroll
    for (int h = 0; h < 2; h++) {
        sacc[h] += __shfl_xor_sync(~0u, sacc[h], 1);
        sacc[h] += __shfl_xor_sync(~0u, sacc[h], 2);
    }
    __syncthreads();
    if ((lane & 3) == 0) {
        #pragma unroll
        for (int h = 0; h < 2; h++)
            Red[(rw + h * 8 + r) * 2 + (w & 1)] = sacc[h];
    }
    __syncthreads();
    if (t < 64) Sinv[t] = 1.0f / (1e-9f + Red[t*2] + Red[t*2+1]);
    __syncthreads();
    #pragma unroll
    for (int h = 0; h < 2; h++) {
        int row = rw + h * 8 + r;
        float si = Sinv[row];
        float* dst = xrT + (bN + m0 + row) * C;
        #pragma unroll
        for (int j = 0; j < NJ2; j++) {
            int col = cw2 + j * 8 + q2;
            float u0 = fmaf(acc2X[j][2*h],   ILSC, acc2H[j][2*h]);
            float u1 = fmaf(acc2X[j][2*h+1], ILSC, acc2H[j][2*h+1]);
            *(float2*)(dst + col) = make_float2(u0 * si, u1 * si);
        }
    }
}

template<int C>
__global__ void k_diffconv(const float* __restrict__ h, const float* __restrict__ xrT,
                           const float* __restrict__ wt, const float* __restrict__ bt,
                           float* __restrict__ tp) {
    __shared__ float ws[C*C], bs[C];
    int t = threadIdx.x;
    for (int i = t; i < C*C; i += 256) ws[i] = wt[i];
    if (t < C) bs[t] = bt[t];
    __syncthreads();
    int b = blockIdx.y, n = blockIdx.x * 256 + t;
    const float* xs = xrT + ((size_t)b * NN + n) * C;
    float din[C];
    #pragma unroll
    for (int c = 0; c < C; c += 4) {
        float4 xv = *(const float4*)(xs + c);
        din[c]     = h[(b * C + c) * NN + n]     - xv.x;
        din[c + 1] = h[(b * C + c + 1) * NN + n] - xv.y;
        din[c + 2] = h[(b * C + c + 2) * NN + n] - xv.z;
        din[c + 3] = h[(b * C + c + 3) * NN + n] - xv.w;
    }
    for (int o = 0; o < C; o++) {
        float a = bs[o];
        #pragma unroll
        for (int c = 0; c < C; c++) a = fmaf(ws[o * C + c], din[c], a);
        tp[(b * C + o) * NN + n] = a;
    }
}

template<int C>
__global__ void k_resid(const float* __restrict__ h, const float* __restrict__ tp,
                        const float* __restrict__ st2, const float* __restrict__ g,
                        const float* __restrict__ be, float* __restrict__ out) {
    __shared__ float scs, shs;
    int idx = blockIdx.x * 256 + threadIdx.x;
    int c = (idx >> 12) & (C - 1);
    if (threadIdx.x == 0) bn_coef8(st2, g, be, c, scs, shs);
    __syncthreads();
    out[idx] = h[idx] + fmaxf(fmaf(scs, tp[idx], shs), 0.f);
}

__global__ void k_max(const float* __restrict__ d, float* __restrict__ gf) {
    int bc = blockIdx.x;
    const float* p = d + bc * NN;
    float m = -1e30f;
    for (int i = threadIdx.x; i < NN; i += 256) m = fmaxf(m, p[i]);
    __shared__ float sm_[8];
    for (int o = 16; o; o >>= 1) m = fmaxf(m, __shfl_down_sync(~0u, m, o));
    if ((threadIdx.x & 31) == 0) sm_[threadIdx.x >> 5] = m;
    __syncthreads();
    if (threadIdx.x == 0) {
        float M = sm_[0];
        #pragma unroll
        for (int i = 1; i < 8; i++) M = fmaxf(M, sm_[i]);
        gf[bc] = M;
    }
}

__global__ void k_concatconv(const float* __restrict__ h3, const float* __restrict__ gf1,
                             const float* __restrict__ w3, const float* __restrict__ b3,
                             float* __restrict__ y3) {
    __shared__ float ws[4096], K[64];
    int t = threadIdx.x, b = blockIdx.y;
    for (int i = t; i < 4096; i += 256) ws[i] = w3[i];
    __syncthreads();
    if (t < 64) {
        float a = b3[t];
        #pragma unroll
        for (int c = 0; c < 32; c++) a = fmaf(ws[t * 64 + 32 + c], gf1[b * 32 + c], a);
        K[t] = a;
    }
    __syncthreads();
    int n = blockIdx.x * 256 + t;
    float in[32];
    #pragma unroll
    for (int c = 0; c < 32; c++) in[c] = h3[(b * 32 + c) * NN + n];
    for (int o = 0; o < 64; o++) {
        float a = K[o];
        #pragma unroll
        for (int c = 0; c < 32; c++) a = fmaf(ws[o * 64 + c], in[c], a);
        y3[(b * 64 + o) * NN + n] = a;
    }
}

extern "C" void kernel_launch(void* const* d_in, const int* in_sizes, int n_in,
                              void* d_out, int out_size) {
    const float *x = (const float*)d_in[0], *w1 = (const float*)d_in[1], *b1 = (const float*)d_in[2],
        *g1 = (const float*)d_in[3], *be1 = (const float*)d_in[4], *w2 = (const float*)d_in[5],
        *b2 = (const float*)d_in[6], *g2 = (const float*)d_in[7], *be2 = (const float*)d_in[8],
        *a1_wqk = (const float*)d_in[9], *a1_wv = (const float*)d_in[10], *a1_bv = (const float*)d_in[11],
        *a1_wt = (const float*)d_in[12], *a1_bt = (const float*)d_in[13], *a1_g = (const float*)d_in[14],
        *a1_b = (const float*)d_in[15], *w3 = (const float*)d_in[16], *b3 = (const float*)d_in[17],
        *g3 = (const float*)d_in[18], *be3 = (const float*)d_in[19], *a2_wqk = (const float*)d_in[20],
        *a2_wv = (const float*)d_in[21], *a2_bv = (const float*)d_in[22], *a2_wt = (const float*)d_in[23],
        *a2_bt = (const float*)d_in[24], *a2_g = (const float*)d_in[25], *a2_b = (const float*)d_in[26];

    float* S = nullptr;
    cudaGetSymbolAddress((void**)&S, SCR);
    float *y1 = S, *y2 = S + BUF, *h2 = S + 2*BUF, *qkB = S + 3*BUF, *vB = S + 4*BUF,
          *xrT = S + 5*BUF, *tpb = S + 6*BUF, *h3 = S + 7*BUF;
    float *Mr = S + 8*BUF, *iL = Mr + BB*NN, *gf1 = iL + BB*NN, *st2 = gf1 + 256 + 5*128;
    hf *qh = (hf*)qkB, *ql = qh + (size_t)BB*NN*64;
    hf *vh = (hf*)vB, *vl = vh + (size_t)BB*NN*64;
    float* outh = (float*)d_out;
    float* outgf = outh + BB * 64 * NN;

    // smem bytes: 2048 header + (Ah+Al = 2*64*S, B dbuf = 2*256*S) halves
    int smA32 = 2048 + (2*64*40 + 2*256*40) * 2;
    int smA64 = 2048 + (2*64*72 + 2*256*72) * 2;
    int smB32 = 2048 + (2*64*40 + 2*128*40 + 2*2*32*72 + 2*64*72) * 2;
    int smB64 = 2048 + (2*64*72 + 2*128*72 + 2*2*64*72 + 2*64*72) * 2;
    cudaFuncSetAttribute(k_gramA<32>, cudaFuncAttributeMaxDynamicSharedMemorySize, smA32);
    cudaFuncSetAttribute(k_gramA<64>, cudaFuncAttributeMaxDynamicSharedMemorySize, smA64);
    cudaFuncSetAttribute(k_gramB<32>, cudaFuncAttributeMaxDynamicSharedMemorySize, smB32);
    cudaFuncSetAttribute(k_gramB<64>, cudaFuncAttributeMaxDynamicSharedMemorySize, smB64);

    dim3 gN(NN / 256, BB), gA(64, BB);
    k_conv1<<<gN, 256>>>(x, w1, b1, y1);
    k_stats1<<<dim3(32, BB), 256>>>(y1, 32, st2);
    k_bnconv32<<<gN, 256>>>(y1, st2, g1, be1, w2, b2, y2);
    k_stats1<<<dim3(32, BB), 256>>>(y2, 32, st2);
    k_bnqkv<32><<<gN, 256>>>(y2, st2, g2, be2, a1_wqk, a1_wv, a1_bv, h2, qh, ql, vh, vl);
    k_gramA<32><<<gA, 256, smA32>>>(qh, ql, Mr, iL);
    k_gramB<32><<<gA, 256, smB32>>>(qh, ql, vh, vl, Mr, iL, xrT);
    k_diffconv<32><<<gN, 256>>>(h2, xrT, a1_wt, a1_bt, tpb);
    k_stats1<<<dim3(32, BB), 256>>>(tpb, 32, st2);
    k_resid<32><<<BB*32*NN/256, 256>>>(h2, tpb, st2, a1_g, a1_b, h3);
    k_max<<<BB * 32, 256>>>(h3, gf1);
    k_concatconv<<<gN, 256>>>(h3, gf1, w3, b3, y2);
    k_stats1<<<dim3(64, BB), 256>>>(y2, 64, st2);
    k_bnqkv<64><<<gN, 256>>>(y2, st2, g3, be3, a2_wqk, a2_wv, a2_bv, y1, qh, ql, vh, vl);
    k_gramA<64><<<gA, 256, smA64>>>(qh, ql, Mr, iL);
    k_gramB<64><<<gA, 256, smB64>>>(qh, ql, vh, vl, Mr, iL, xrT);
    k_diffconv<64><<<gN, 256>>>(y1, xrT, a2_wt, a2_bt, tpb);
    k_stats1<<<dim3(64, BB), 256>>>(tpb, 64, st2);
    k_resid<64><<<BB*64*NN/256, 256>>>(y1, tpb, st2, a2_g, a2_b, outh);
    k_max<<<BB * 64, 256>>>(outh, outgf);
}

// round 14
// speedup vs baseline: 1.0923x; 1.0923x over previous
#include <cuda_runtime.h>
#include <cuda_fp16.h>
#include <cstdint>

#define NN 4096
#define BB 8
#define NBTOT (BB*NN)
#define LSC 2048.0f
#define ILSC (1.0f/2048.0f)
typedef __half hf;

__device__ __forceinline__ uint32_t pk2(float a, float b) {
    __half2 h = __floats2half2_rn(a, b);
    return *(uint32_t*)&h;
}
__device__ __forceinline__ void mma16(float* d, const uint32_t* a, uint32_t b0, uint32_t b1) {
    asm volatile("mma.sync.aligned.m16n8k16.row.col.f32.f16.f16.f32 "
        "{%0,%1,%2,%3}, {%4,%5,%6,%7}, {%8,%9}, {%0,%1,%2,%3};"
        : "+f"(d[0]), "+f"(d[1]), "+f"(d[2]), "+f"(d[3])
        : "r"(a[0]), "r"(a[1]), "r"(a[2]), "r"(a[3]), "r"(b0), "r"(b1));
}
__device__ __forceinline__ void ldfA(uint32_t* f, const hf* base, int S, int rb, int kb, int r, int q2) {
    f[0] = *(const uint32_t*)(base + (rb + r) * S + kb + q2);
    f[1] = *(const uint32_t*)(base + (rb + r + 8) * S + kb + q2);
    f[2] = *(const uint32_t*)(base + (rb + r) * S + kb + q2 + 8);
    f[3] = *(const uint32_t*)(base + (rb + r + 8) * S + kb + q2 + 8);
}
__device__ __forceinline__ void cpa16(const void* s, const void* g) {
    uint32_t a = (uint32_t)__cvta_generic_to_shared(s);
    asm volatile("cp.async.ca.shared.global [%0], [%1], 16;" :: "r"(a), "l"(g) : "memory");
}
#define CPA_COMMIT() asm volatile("cp.async.commit_group;" ::: "memory")
#define CPA_WAIT()   asm volatile("cp.async.wait_group 0;" ::: "memory")

template<int C, int ROWS, int S>
__device__ __forceinline__ void cpa_tile(hf* sh, hf* sl, const hf* gh, const hf* gl, size_t base, int t) {
    constexpr int OPS = ROWS * C / 8;
    #pragma unroll
    for (int i = 0; i < (OPS + 255) / 256; i++) {
        int idx = t + i * 256;
        if ((OPS & 255) == 0 || idx < OPS) {
            int row = idx / (C / 8), cu = idx % (C / 8);
            size_t go = base + (size_t)row * C + cu * 8;
            cpa16(sh + row * S + cu * 8, gh + go);
            cpa16(sl + row * S + cu * 8, gl + go);
        }
    }
}
template<int C, int SE>
__device__ __forceinline__ void cpa_vtile(hf* sh, hf* sl, const hf* gh, const hf* gl,
                                          size_t bC, int n0, int t) {
    constexpr int OPS = C * 8;
    #pragma unroll
    for (int i = 0; i < (OPS + 255) / 256; i++) {
        int idx = t + i * 256;
        if ((OPS & 255) == 0 || idx < OPS) {
            int row = idx >> 3, cu = idx & 7;
            size_t go = (bC + row) * NN + n0 + cu * 8;
            cpa16(sh + row * SE + cu * 8, gh + go);
            cpa16(sl + row * SE + cu * 8, gl + go);
        }
    }
}

#define BUF 2097152
__device__ float SCR[8*BUF + 2*BB*NN + 256 + 5*128 + 1024];

__device__ __forceinline__ void bn_coef8(const float* __restrict__ st2, const float* __restrict__ g,
                                         const float* __restrict__ be, int c, float& sc, float& sh) {
    float S = 0.f, Q = 0.f;
    #pragma unroll
    for (int b = 0; b < BB; b++) { S += st2[b * 128 + c]; Q += st2[b * 128 + 64 + c]; }
    const float inv = 1.0f / (float)NBTOT;
    float mean = S * inv;
    float var = Q * inv - mean * mean;
    float r = rsqrtf(var + 1e-5f);
    sc = g[c] * r; sh = be[c] - sc * mean;
}

__global__ void k_stats1(const float* __restrict__ d, int C, float* __restrict__ st2) {
    int c = blockIdx.x, b = blockIdx.y;
    const float* p = d + (b * C + c) * NN;
    float s = 0.f, sq = 0.f;
    for (int i = threadIdx.x; i < NN; i += 256) { float v = p[i]; s += v; sq += v * v; }
    __shared__ float shs[8], shq[8];
    for (int o = 16; o; o >>= 1) { s += __shfl_down_sync(~0u, s, o); sq += __shfl_down_sync(~0u, sq, o); }
    if ((threadIdx.x & 31) == 0) { shs[threadIdx.x >> 5] = s; shq[threadIdx.x >> 5] = sq; }
    __syncthreads();
    if (threadIdx.x == 0) {
        float S = 0.f, Q = 0.f;
        #pragma unroll
        for (int i = 0; i < 8; i++) { S += shs[i]; Q += shq[i]; }
        st2[b * 128 + c] = S; st2[b * 128 + 64 + c] = Q;
    }
}

__global__ void k_conv1(const float* __restrict__ x, const float* __restrict__ w,
                        const float* __restrict__ bias, float* __restrict__ y) {
    __shared__ float ws[192], bs[32];
    int t = threadIdx.x;
    if (t < 192) ws[t] = w[t];
    if (t < 32) bs[t] = bias[t];
    __syncthreads();
    int b = blockIdx.y, n = blockIdx.x * 256 + t;
    float in[6];
    #pragma unroll
    for (int c = 0; c < 6; c++) in[c] = x[(b * 6 + c) * NN + n];
    #pragma unroll
    for (int o = 0; o < 32; o++) {
        float a = bs[o];
        #pragma unroll
        for (int c = 0; c < 6; c++) a = fmaf(ws[o * 6 + c], in[c], a);
        y[(b * 32 + o) * NN + n] = a;
    }
}

__global__ void k_bnconv32(const float* __restrict__ yin, const float* __restrict__ st2,
                           const float* __restrict__ g, const float* __restrict__ be,
                           const float* __restrict__ w, const float* __restrict__ bias,
                           float* __restrict__ yout) {
    __shared__ float ws[1024], bs[32], sc[32], sh[32];
    int t = threadIdx.x;
    for (int i = t; i < 1024; i += 256) ws[i] = w[i];
    if (t < 32) { bs[t] = bias[t]; bn_coef8(st2, g, be, t, sc[t], sh[t]); }
    __syncthreads();
    int b = blockIdx.y, n = blockIdx.x * 256 + t;
    float in[32];
    #pragma unroll
    for (int c = 0; c < 32; c++) in[c] = fmaxf(fmaf(sc[c], yin[(b * 32 + c) * NN + n], sh[c]), 0.f);
    for (int o = 0; o < 32; o++) {
        float a = bs[o];
        #pragma unroll
        for (int c = 0; c < 32; c++) a = fmaf(ws[o * 32 + c], in[c], a);
        yout[(b * 32 + o) * NN + n] = a;
    }
}

template<int C>
__global__ void k_bnqkv(const float* __restrict__ yin, const float* __restrict__ st2,
                        const float* __restrict__ g, const float* __restrict__ be,
                        const float* __restrict__ wqk, const float* __restrict__ wv,
                        const float* __restrict__ bv, float* __restrict__ h,
                        hf* __restrict__ qh, hf* __restrict__ ql,
                        hf* __restrict__ vh, hf* __restrict__ vl) {
    __shared__ float wq_s[C*C], wv_s[C*C], bvs[C], sc[C], sh[C];
    int t = threadIdx.x;
    for (int i = t; i < C*C; i += 256) { wq_s[i] = wqk[i]; wv_s[i] = wv[i]; }
    if (t < C) { bvs[t] = bv[t]; bn_coef8(st2, g, be, t, sc[t], sh[t]); }
    __syncthreads();
    int b = blockIdx.y, n = blockIdx.x * 256 + t;
    float in[C];
    #pragma unroll
    for (int c = 0; c < C; c++) {
        float val = fmaxf(fmaf(sc[c], yin[(b * C + c) * NN + n], sh[c]), 0.f);
        in[c] = val;
        h[(b * C + c) * NN + n] = val;
    }
    size_t qoff = ((size_t)b * NN + n) * C;
    for (int og = 0; og < C; og += 4) {
        uint32_t uh[2], ul[2];
        #pragma unroll
        for (int oo = 0; oo < 4; oo += 2) {
            float q0 = 0.f, q1 = 0.f, av0 = bvs[og+oo], av1 = bvs[og+oo+1];
            #pragma unroll
            for (int c = 0; c < C; c++) {
                q0 = fmaf(wq_s[(og+oo) * C + c], in[c], q0);
                q1 = fmaf(wq_s[(og+oo+1) * C + c], in[c], q1);
                av0 = fmaf(wv_s[(og+oo) * C + c], in[c], av0);
                av1 = fmaf(wv_s[(og+oo+1) * C + c], in[c], av1);
            }
            hf h0 = __float2half_rn(q0), h1 = __float2half_rn(q1);
            uh[oo>>1] = ((uint32_t)__half_as_ushort(h1) << 16) | __half_as_ushort(h0);
            ul[oo>>1] = pk2((q0 - __half2float(h0)) * LSC, (q1 - __half2float(h1)) * LSC);
            hf v0 = __float2half_rn(av0), v1 = __float2half_rn(av1);
            vh[(b * C + og+oo) * NN + n] = v0;
            vh[(b * C + og+oo+1) * NN + n] = v1;
            vl[(b * C + og+oo) * NN + n] = __float2half_rn((av0 - __half2float(v0)) * LSC);
            vl[(b * C + og+oo+1) * NN + n] = __float2half_rn((av1 - __half2float(v1)) * LSC);
        }
        *(uint2*)(qh + qoff + og) = make_uint2(uh[0], uh[1]);
        *(uint2*)(ql + qoff + og) = make_uint2(ul[0], ul[1]);
    }
}

// ---- pass A: 128-row tiles, cp.async dbuf B; per-row online (M, L) ----
template<int C>
__global__ void __launch_bounds__(256) k_gramA(const hf* __restrict__ qh, const hf* __restrict__ ql,
                                               float* __restrict__ Mr, float* __restrict__ iLv) {
    constexpr int S = C + 8;
    extern __shared__ float smf[];
    float *RM = smf, *RL = smf + 256;
    hf* Ah = (hf*)(smf + 512);
    hf* Al = Ah + 128 * S;
    hf* Bbase = Al + 128 * S;      // dbuf: each 2*128*S halves
    const int t = threadIdx.x, w = t >> 5, lane = t & 31;
    const int b = blockIdx.y, n0 = blockIdx.x * 128;
    const int rw = (w >> 1) * 32, cw = (w & 1) * 64;
    const int r = lane >> 2, q2 = (lane & 3) * 2;
    const size_t bN = (size_t)b * NN;
    cpa_tile<C, 128, S>(Ah, Al, qh, ql, (bN + n0) * C, t);
    cpa_tile<C, 128, S>(Bbase, Bbase + 128 * S, qh, ql, bN * C, t);
    CPA_COMMIT();
    float Mv[4], Lv[4];
    #pragma unroll
    for (int i = 0; i < 4; i++) { Mv[i] = -1e30f; Lv[i] = 0.f; }
    for (int mt = 0; mt < 32; mt++) {
        CPA_WAIT();
        __syncthreads();
        hf* Bh = Bbase + (mt & 1) * 256 * S;
        hf* Bl = Bh + 128 * S;
        if (mt + 1 < 32) {
            hf* Bn = Bbase + ((mt + 1) & 1) * 256 * S;
            cpa_tile<C, 128, S>(Bn, Bn + 128 * S, qh, ql, (bN + (mt + 1) * 128) * C, t);
            CPA_COMMIT();
        }
        float accH[2][8][4], accX[2][8][4];
        #pragma unroll
        for (int rf = 0; rf < 2; rf++)
            #pragma unroll
            for (int j = 0; j < 8; j++)
                #pragma unroll
                for (int e = 0; e < 4; e++) { accH[rf][j][e] = 0.f; accX[rf][j][e] = 0.f; }
        #pragma unroll
        for (int ks = 0; ks < C / 16; ks++) {
            int kb = ks * 16;
            uint32_t ah[2][4], al[2][4];
            #pragma unroll
            for (int rf = 0; rf < 2; rf++) {
                ldfA(ah[rf], Ah, S, rw + rf * 16, kb, r, q2);
                ldfA(al[rf], Al, S, rw + rf * 16, kb, r, q2);
            }
            #pragma unroll
            for (int j = 0; j < 8; j++) {
                int cb = cw + j * 8;
                uint32_t bh0 = *(const uint32_t*)(Bh + (cb + r) * S + kb + q2);
                uint32_t bh1 = *(const uint32_t*)(Bh + (cb + r) * S + kb + q2 + 8);
                uint32_t bl0 = *(const uint32_t*)(Bl + (cb + r) * S + kb + q2);
                uint32_t bl1 = *(const uint32_t*)(Bl + (cb + r) * S + kb + q2 + 8);
                #pragma unroll
                for (int rf = 0; rf < 2; rf++) {
                    mma16(accH[rf][j], ah[rf], bh0, bh1);
                    mma16(accX[rf][j], ah[rf], bl0, bl1);
                    mma16(accX[rf][j], al[rf], bh0, bh1);
                }
            }
        }
        #pragma unroll
        for (int rf = 0; rf < 2; rf++)
            #pragma unroll
            for (int h = 0; h < 2; h++) {
                int i = rf * 2 + h;
                float sv[16];
                #pragma unroll
                for (int j = 0; j < 8; j++) {
                    sv[2*j]   = fmaf(accX[rf][j][2*h],   ILSC, accH[rf][j][2*h]);
                    sv[2*j+1] = fmaf(accX[rf][j][2*h+1], ILSC, accH[rf][j][2*h+1]);
                }
                float tm = -1e30f;
                #pragma unroll
                for (int j = 0; j < 16; j++) tm = fmaxf(tm, sv[j]);
                float Mn = fmaxf(Mv[i], tm);
                float l = Lv[i] * __expf(Mv[i] - Mn);
                #pragma unroll
                for (int j = 0; j < 16; j++) l += __expf(sv[j] - Mn);
                Mv[i] = Mn; Lv[i] = l;
            }
        __syncthreads();
    }
    #pragma unroll
    for (int i = 0; i < 4; i++)
        #pragma unroll
        for (int o = 1; o <= 2; o <<= 1) {
            float M2 = __shfl_xor_sync(~0u, Mv[i], o);
            float L2 = __shfl_xor_sync(~0u, Lv[i], o);
            float Mn = fmaxf(Mv[i], M2);
            Lv[i] = Lv[i] * __expf(Mv[i] - Mn) + L2 * __expf(M2 - Mn);
            Mv[i] = Mn;
        }
    __syncthreads();
    if ((lane & 3) == 0) {
        #pragma unroll
        for (int i = 0; i < 4; i++) {
            int row = rw + (i >> 1) * 16 + (i & 1) * 8 + r;
            RM[row * 2 + (w & 1)] = Mv[i];
            RL[row * 2 + (w & 1)] = Lv[i];
        }
    }
    __syncthreads();
    if (t < 128) {
        float M0 = RM[t*2], M1 = RM[t*2+1], L0 = RL[t*2], L1 = RL[t*2+1];
        float Mn = fmaxf(M0, M1);
        float L = L0 * __expf(M0 - Mn) + L1 * __expf(M1 - Mn);
        Mr[b * NN + n0 + t] = Mn;
        iLv[b * NN + n0 + t] = 1.0f / L;
    }
}

// ---- pass B: 128 m-rows, cp.async dbuf Qn/V/M/L; E hi+lo; xr = E x V ----
template<int C>
__global__ void __launch_bounds__(256) k_gramB(const hf* __restrict__ qh, const hf* __restrict__ ql,
                                               const hf* __restrict__ vhp, const hf* __restrict__ vlp,
                                               const float* __restrict__ Mr, const float* __restrict__ iLv,
                                               float* __restrict__ xrT) {
    constexpr int S = C + 8, SE = 72, NJ2 = C / 16;
    extern __shared__ float smf[];
    float *MshB = smf;          // [2][64]
    float *LshB = smf + 128;    // [2][64]
    float *Red  = smf + 256;    // 256
    float *Sinv = smf + 512;    // 128
    hf* Qmh = (hf*)(smf + 640);
    hf* Qml = Qmh + 128 * S;
    hf* Qbase = Qml + 128 * S;           // dbuf: each 2*64*S
    hf* Vbase = Qbase + 2 * 128 * S;     // dbuf: each 2*C*SE
    hf* Eh = Vbase + 2 * 2 * C * SE;
    hf* El = Eh + 128 * SE;
    const int t = threadIdx.x, w = t >> 5, lane = t & 31;
    const int b = blockIdx.y, m0 = blockIdx.x * 128;
    const int rw = (w >> 1) * 32, cw = (w & 1) * 32, cw2 = (w & 1) * (C / 2);
    const int r = lane >> 2, q2 = (lane & 3) * 2;
    const size_t bN = (size_t)b * NN, bC = (size_t)b * C;
    cpa_tile<C, 128, S>(Qmh, Qml, qh, ql, (bN + m0) * C, t);
    cpa_tile<C, 64, S>(Qbase, Qbase + 64 * S, qh, ql, bN * C, t);
    cpa_vtile<C, SE>(Vbase, Vbase + C * SE, vhp, vlp, bC, 0, t);
    if (t < 16) cpa16(MshB + t * 4, Mr + bN + t * 4);
    else if (t < 32) cpa16(LshB + (t - 16) * 4, iLv + bN + (t - 16) * 4);
    CPA_COMMIT();
    float acc2H[2][NJ2][4], acc2X[2][NJ2][4];
    #pragma unroll
    for (int rf = 0; rf < 2; rf++)
        #pragma unroll
        for (int j = 0; j < NJ2; j++)
            #pragma unroll
            for (int e = 0; e < 4; e++) { acc2H[rf][j][e] = 0.f; acc2X[rf][j][e] = 0.f; }
    float sacc[4] = {0.f, 0.f, 0.f, 0.f};
    for (int nt = 0; nt < 64; nt++) {
        CPA_WAIT();
        __syncthreads();
        int bi = nt & 1;
        hf* Qnh = Qbase + bi * 128 * S;
        hf* Qnl = Qnh + 64 * S;
        hf* Vh = Vbase + bi * 2 * C * SE;
        hf* Vl = Vh + C * SE;
        const float* Msh = MshB + bi * 64;
        const float* Lsh = LshB + bi * 64;
        if (nt + 1 < 64) {
            int bj = (nt + 1) & 1, n1 = (nt + 1) * 64;
            hf* Qn2 = Qbase + bj * 128 * S;
            hf* V2 = Vbase + bj * 2 * C * SE;
            cpa_tile<C, 64, S>(Qn2, Qn2 + 64 * S, qh, ql, (bN + n1) * C, t);
            cpa_vtile<C, SE>(V2, V2 + C * SE, vhp, vlp, bC, n1, t);
            if (t < 16) cpa16(MshB + bj * 64 + t * 4, Mr + bN + n1 + t * 4);
            else if (t < 32) cpa16(LshB + bj * 64 + (t - 16) * 4, iLv + bN + n1 + (t - 16) * 4);
            CPA_COMMIT();
        }
        float accS[2][4][4], accSX[2][4][4];
        #pragma unroll
        for (int rf = 0; rf < 2; rf++)
            #pragma unroll
            for (int j = 0; j < 4; j++)
                #pragma unroll
                for (int e = 0; e < 4; e++) { accS[rf][j][e] = 0.f; accSX[rf][j][e] = 0.f; }
        #pragma unroll
        for (int ks = 0; ks < C / 16; ks++) {
            int kb = ks * 16;
            uint32_t ah[2][4], al[2][4];
            #pragma unroll
            for (int rf = 0; rf < 2; rf++) {
                ldfA(ah[rf], Qmh, S, rw + rf * 16, kb, r, q2);
                ldfA(al[rf], Qml, S, rw + rf * 16, kb, r, q2);
            }
            #pragma unroll
            for (int j = 0; j < 4; j++) {
                int cb = cw + j * 8;
                uint32_t bh0 = *(const uint32_t*)(Qnh + (cb + r) * S + kb + q2);
                uint32_t bh1 = *(const uint32_t*)(Qnh + (cb + r) * S + kb + q2 + 8);
                uint32_t bl0 = *(const uint32_t*)(Qnl + (cb + r) * S + kb + q2);
                uint32_t bl1 = *(const uint32_t*)(Qnl + (cb + r) * S + kb + q2 + 8);
                #pragma unroll
                for (int rf = 0; rf < 2; rf++) {
                    mma16(accS[rf][j], ah[rf], bh0, bh1);
                    mma16(accSX[rf][j], ah[rf], bl0, bl1);
                    mma16(accSX[rf][j], al[rf], bh0, bh1);
                }
            }
        }
        #pragma unroll
        for (int rf = 0; rf < 2; rf++)
            #pragma unroll
            for (int h = 0; h < 2; h++) {
                int row = rw + rf * 16 + h * 8 + r;
                #pragma unroll
                for (int j = 0; j < 4; j++) {
                    int col = cw + j * 8 + q2;
                    float s0 = fmaf(accSX[rf][j][2*h],   ILSC, accS[rf][j][2*h]);
                    float s1 = fmaf(accSX[rf][j][2*h+1], ILSC, accS[rf][j][2*h+1]);
                    float e0 = __expf(s0 - Msh[col])     * Lsh[col];
                    float e1 = __expf(s1 - Msh[col + 1]) * Lsh[col + 1];
                    sacc[rf * 2 + h] += e0 + e1;
                    hf eh0 = __float2half_rn(e0), eh1 = __float2half_rn(e1);
                    *(uint32_t*)(Eh + row * SE + col) =
                        ((uint32_t)__half_as_ushort(eh1) << 16) | __half_as_ushort(eh0);
                    *(uint32_t*)(El + row * SE + col) =
                        pk2((e0 - __half2float(eh0)) * LSC, (e1 - __half2float(eh1)) * LSC);
                }
            }
        __syncthreads();
        #pragma unroll
        for (int ks = 0; ks < 4; ks++) {
            int kb = ks * 16;
            uint32_t ef[2][4], efl[2][4];
            #pragma unroll
            for (int rf = 0; rf < 2; rf++) {
                ldfA(ef[rf], Eh, SE, rw + rf * 16, kb, r, q2);
                ldfA(efl[rf], El, SE, rw + rf * 16, kb, r, q2);
            }
            #pragma unroll
            for (int j = 0; j < NJ2; j++) {
                int cc = cw2 + j * 8;
                uint32_t bh0 = *(const uint32_t*)(Vh + (cc + r) * SE + kb + q2);
                uint32_t bh1 = *(const uint32_t*)(Vh + (cc + r) * SE + kb + q2 + 8);
                uint32_t bl0 = *(const uint32_t*)(Vl + (cc + r) * SE + kb + q2);
                uint32_t bl1 = *(const uint32_t*)(Vl + (cc + r) * SE + kb + q2 + 8);
                #pragma unroll
                for (int rf = 0; rf < 2; rf++) {
                    mma16(acc2H[rf][j], ef[rf], bh0, bh1);
                    mma16(acc2X[rf][j], ef[rf], bl0, bl1);
                    mma16(acc2X[rf][j], efl[rf], bh0, bh1);
                }
            }
        }
    }
    #pragma unroll
    for (int i = 0; i < 4; i++) {
        sacc[i] += __shfl_xor_sync(~0u, sacc[i], 1);
        sacc[i] += __shfl_xor_sync(~0u, sacc[i], 2);
    }
    __syncthreads();
    if ((lane & 3) == 0) {
        #pragma unroll
        for (int i = 0; i < 4; i++) {
            int row = rw + (i >> 1) * 16 + (i & 1) * 8 + r;
            Red[row * 2 + (w & 1)] = sacc[i];
        }
    }
    __syncthreads();
    if (t < 128) Sinv[t] = 1.0f / (1e-9f + Red[t*2] + Red[t*2+1]);
    __syncthreads();
    #pragma unroll
    for (int rf = 0; rf < 2; rf++)
        #pragma unroll
        for (int h = 0; h < 2; h++) {
            int row = rw + rf * 16 + h * 8 + r;
            float si = Sinv[row];
            float* dst = xrT + (bN + m0 + row) * C;
            #pragma unroll
            for (int j = 0; j < NJ2; j++) {
                int col = cw2 + j * 8 + q2;
                float u0 = fmaf(acc2X[rf][j][2*h],   ILSC, acc2H[rf][j][2*h]);
                float u1 = fmaf(acc2X[rf][j][2*h+1], ILSC, acc2H[rf][j][2*h+1]);
                *(float2*)(dst + col) = make_float2(u0 * si, u1 * si);
            }
        }
}

template<int C>
__global__ void k_diffconv(const float* __restrict__ h, const float* __restrict__ xrT,
                           const float* __restrict__ wt, const float* __restrict__ bt,
                           float* __restrict__ tp) {
    __shared__ float ws[C*C], bs[C];
    int t = threadIdx.x;
    for (int i = t; i < C*C; i += 256) ws[i] = wt[i];
    if (t < C) bs[t] = bt[t];
    __syncthreads();
    int b = blockIdx.y, n = blockIdx.x * 256 + t;
    const float* xs = xrT + ((size_t)b * NN + n) * C;
    float din[C];
    #pragma unroll
    for (int c = 0; c < C; c += 4) {
        float4 xv = *(const float4*)(xs + c);
        din[c]     = h[(b * C + c) * NN + n]     - xv.x;
        din[c + 1] = h[(b * C + c + 1) * NN + n] - xv.y;
        din[c + 2] = h[(b * C + c + 2) * NN + n] - xv.z;
        din[c + 3] = h[(b * C + c + 3) * NN + n] - xv.w;
    }
    for (int o = 0; o < C; o++) {
        float a = bs[o];
        #pragma unroll
        for (int c = 0; c < C; c++) a = fmaf(ws[o * C + c], din[c], a);
        tp[(b * C + o) * NN + n] = a;
    }
}

template<int C>
__global__ void k_resid(const float* __restrict__ h, const float* __restrict__ tp,
                        const float* __restrict__ st2, const float* __restrict__ g,
                        const float* __restrict__ be, float* __restrict__ out) {
    __shared__ float scs, shs;
    int idx = blockIdx.x * 256 + threadIdx.x;
    int c = (idx >> 12) & (C - 1);
    if (threadIdx.x == 0) bn_coef8(st2, g, be, c, scs, shs);
    __syncthreads();
    out[idx] = h[idx] + fmaxf(fmaf(scs, tp[idx], shs), 0.f);
}

__global__ void k_max(const float* __restrict__ d, float* __restrict__ gf) {
    int bc = blockIdx.x;
    const float* p = d + bc * NN;
    float m = -1e30f;
    for (int i = threadIdx.x; i < NN; i += 256) m = fmaxf(m, p[i]);
    __shared__ float sm_[8];
    for (int o = 16; o; o >>= 1) m = fmaxf(m, __shfl_down_sync(~0u, m, o));
    if ((threadIdx.x & 31) == 0) sm_[threadIdx.x >> 5] = m;
    __syncthreads();
    if (threadIdx.x == 0) {
        float M = sm_[0];
        #pragma unroll
        for (int i = 1; i < 8; i++) M = fmaxf(M, sm_[i]);
        gf[bc] = M;
    }
}

__global__ void k_concatconv(const float* __restrict__ h3, const float* __restrict__ gf1,
                             const float* __restrict__ w3, const float* __restrict__ b3,
                             float* __restrict__ y3) {
    __shared__ float ws[4096], K[64];
    int t = threadIdx.x, b = blockIdx.y;
    for (int i = t; i < 4096; i += 256) ws[i] = w3[i];
    __syncthreads();
    if (t < 64) {
        float a = b3[t];
        #pragma unroll
        for (int c = 0; c < 32; c++) a = fmaf(ws[t * 64 + 32 + c], gf1[b * 32 + c], a);
        K[t] = a;
    }
    __syncthreads();
    int n = blockIdx.x * 256 + t;
    float in[32];
    #pragma unroll
    for (int c = 0; c < 32; c++) in[c] = h3[(b * 32 + c) * NN + n];
    for (int o = 0; o < 64; o++) {
        float a = K[o];
        #pragma unroll
        for (int c = 0; c < 32; c++) a = fmaf(ws[o * 64 + c], in[c], a);
        y3[(b * 64 + o) * NN + n] = a;
    }
}

extern "C" void kernel_launch(void* const* d_in, const int* in_sizes, int n_in,
                              void* d_out, int out_size) {
    const float *x = (const float*)d_in[0], *w1 = (const float*)d_in[1], *b1 = (const float*)d_in[2],
        *g1 = (const float*)d_in[3], *be1 = (const float*)d_in[4], *w2 = (const float*)d_in[5],
        *b2 = (const float*)d_in[6], *g2 = (const float*)d_in[7], *be2 = (const float*)d_in[8],
        *a1_wqk = (const float*)d_in[9], *a1_wv = (const float*)d_in[10], *a1_bv = (const float*)d_in[11],
        *a1_wt = (const float*)d_in[12], *a1_bt = (const float*)d_in[13], *a1_g = (const float*)d_in[14],
        *a1_b = (const float*)d_in[15], *w3 = (const float*)d_in[16], *b3 = (const float*)d_in[17],
        *g3 = (const float*)d_in[18], *be3 = (const float*)d_in[19], *a2_wqk = (const float*)d_in[20],
        *a2_wv = (const float*)d_in[21], *a2_bv = (const float*)d_in[22], *a2_wt = (const float*)d_in[23],
        *a2_bt = (const float*)d_in[24], *a2_g = (const float*)d_in[25], *a2_b = (const float*)d_in[26];

    float* S = nullptr;
    cudaGetSymbolAddress((void**)&S, SCR);
    float *y1 = S, *y2 = S + BUF, *h2 = S + 2*BUF, *qkB = S + 3*BUF, *vB = S + 4*BUF,
          *xrT = S + 5*BUF, *tpb = S + 6*BUF, *h3 = S + 7*BUF;
    float *Mr = S + 8*BUF, *iL = Mr + BB*NN, *gf1 = iL + BB*NN, *st2 = gf1 + 256 + 5*128;
    hf *qh = (hf*)qkB, *ql = qh + (size_t)BB*NN*64;
    hf *vh = (hf*)vB, *vl = vh + (size_t)BB*NN*64;
    float* outh = (float*)d_out;
    float* outgf = outh + BB * 64 * NN;

    // gramA: header 2048 + (A 2*128*S + B dbuf 2*2*128*S) halves
    int smA32 = 2048 + (2*128*40 + 4*128*40) * 2;
    int smA64 = 2048 + (2*128*72 + 4*128*72) * 2;
    // gramB: header 2560 + (Qm 2*128*S + Qn dbuf 4*64*S + V dbuf 4*C*72 + E 2*128*72) halves
    int smB32 = 2560 + (2*128*40 + 4*64*40 + 4*32*72 + 2*128*72) * 2;
    int smB64 = 2560 + (2*128*72 + 4*64*72 + 4*64*72 + 2*128*72) * 2;
    cudaFuncSetAttribute(k_gramA<32>, cudaFuncAttributeMaxDynamicSharedMemorySize, smA32);
    cudaFuncSetAttribute(k_gramA<64>, cudaFuncAttributeMaxDynamicSharedMemorySize, smA64);
    cudaFuncSetAttribute(k_gramB<32>, cudaFuncAttributeMaxDynamicSharedMemorySize, smB32);
    cudaFuncSetAttribute(k_gramB<64>, cudaFuncAttributeMaxDynamicSharedMemorySize, smB64);

    dim3 gN(NN / 256, BB), gA(32, BB);
    k_conv1<<<gN, 256>>>(x, w1, b1, y1);
    k_stats1<<<dim3(32, BB), 256>>>(y1, 32, st2);
    k_bnconv32<<<gN, 256>>>(y1, st2, g1, be1, w2, b2, y2);
    k_stats1<<<dim3(32, BB), 256>>>(y2, 32, st2);
    k_bnqkv<32><<<gN, 256>>>(y2, st2, g2, be2, a1_wqk, a1_wv, a1_bv, h2, qh, ql, vh, vl);
    k_gramA<32><<<gA, 256, smA32>>>(qh, ql, Mr, iL);
    k_gramB<32><<<gA, 256, smB32>>>(qh, ql, vh, vl, Mr, iL, xrT);
    k_diffconv<32><<<gN, 256>>>(h2, xrT, a1_wt, a1_bt, tpb);
    k_stats1<<<dim3(32, BB), 256>>>(tpb, 32, st2);
    k_resid<32><<<BB*32*NN/256, 256>>>(h2, tpb, st2, a1_g, a1_b, h3);
    k_max<<<BB * 32, 256>>>(h3, gf1);
    k_concatconv<<<gN, 256>>>(h3, gf1, w3, b3, y2);
    k_stats1<<<dim3(64, BB), 256>>>(y2, 64, st2);
    k_bnqkv<64><<<gN, 256>>>(y2, st2, g3, be3, a2_wqk, a2_wv, a2_bv, y1, qh, ql, vh, vl);
    k_gramA<64><<<gA, 256, smA64>>>(qh, ql, Mr, iL);
    k_gramB<64><<<gA, 256, smB64>>>(qh, ql, vh, vl, Mr, iL, xrT);
    k_diffconv<64><<<gN, 256>>>(y1, xrT, a2_wt, a2_bt, tpb);
    k_stats1<<<dim3(64, BB), 256>>>(tpb, 64, st2);
    k_resid<64><<<BB*64*NN/256, 256>>>(y1, tpb, st2, a2_g, a2_b, outh);
    k_max<<<BB * 64, 256>>>(outh, outgf);
}

// round 15
// speedup vs baseline: 1.1006x; 1.0075x over previous
#include <cuda_runtime.h>
#include <cuda_fp16.h>
#include <cstdint>

#define NN 4096
#define BB 8
#define NBTOT (BB*NN)
#define LSC 2048.0f
#define ILSC (1.0f/2048.0f)
typedef __half hf;

__device__ __forceinline__ uint32_t pk2(float a, float b) {
    __half2 h = __floats2half2_rn(a, b);
    return *(uint32_t*)&h;
}
__device__ __forceinline__ void mma16(float* d, const uint32_t* a, uint32_t b0, uint32_t b1) {
    asm volatile("mma.sync.aligned.m16n8k16.row.col.f32.f16.f16.f32 "
        "{%0,%1,%2,%3}, {%4,%5,%6,%7}, {%8,%9}, {%0,%1,%2,%3};"
        : "+f"(d[0]), "+f"(d[1]), "+f"(d[2]), "+f"(d[3])
        : "r"(a[0]), "r"(a[1]), "r"(a[2]), "r"(a[3]), "r"(b0), "r"(b1));
}
__device__ __forceinline__ void ldfA(uint32_t* f, const hf* base, int S, int rb, int kb, int r, int q2) {
    f[0] = *(const uint32_t*)(base + (rb + r) * S + kb + q2);
    f[1] = *(const uint32_t*)(base + (rb + r + 8) * S + kb + q2);
    f[2] = *(const uint32_t*)(base + (rb + r) * S + kb + q2 + 8);
    f[3] = *(const uint32_t*)(base + (rb + r + 8) * S + kb + q2 + 8);
}
__device__ __forceinline__ void cpa16(const void* s, const void* g) {
    uint32_t a = (uint32_t)__cvta_generic_to_shared(s);
    asm volatile("cp.async.ca.shared.global [%0], [%1], 16;" :: "r"(a), "l"(g) : "memory");
}
#define CPA_COMMIT() asm volatile("cp.async.commit_group;" ::: "memory")
#define CPA_WAIT()   asm volatile("cp.async.wait_group 0;" ::: "memory")

template<int C, int ROWS, int S>
__device__ __forceinline__ void cpa_tile(hf* sh, hf* sl, const hf* gh, const hf* gl, size_t base, int t) {
    constexpr int OPS = ROWS * C / 8;
    #pragma unroll
    for (int i = 0; i < (OPS + 255) / 256; i++) {
        int idx = t + i * 256;
        if ((OPS & 255) == 0 || idx < OPS) {
            int row = idx / (C / 8), cu = idx % (C / 8);
            size_t go = base + (size_t)row * C + cu * 8;
            cpa16(sh + row * S + cu * 8, gh + go);
            cpa16(sl + row * S + cu * 8, gl + go);
        }
    }
}
template<int C, int SE>
__device__ __forceinline__ void cpa_vtile(hf* sh, hf* sl, const hf* gh, const hf* gl,
                                          size_t bC, int n0, int t) {
    constexpr int OPS = C * 8;
    #pragma unroll
    for (int i = 0; i < (OPS + 255) / 256; i++) {
        int idx = t + i * 256;
        if ((OPS & 255) == 0 || idx < OPS) {
            int row = idx >> 3, cu = idx & 7;
            size_t go = (bC + row) * NN + n0 + cu * 8;
            cpa16(sh + row * SE + cu * 8, gh + go);
            cpa16(sl + row * SE + cu * 8, gl + go);
        }
    }
}

#define BUF 2097152
__device__ float SCR[8*BUF + 2*BB*NN + 256 + 5*128 + 1024];

__device__ __forceinline__ void bn_coef8(const float* __restrict__ st2, const float* __restrict__ g,
                                         const float* __restrict__ be, int c, float& sc, float& sh) {
    float S = 0.f, Q = 0.f;
    #pragma unroll
    for (int b = 0; b < BB; b++) { S += st2[b * 128 + c]; Q += st2[b * 128 + 64 + c]; }
    const float inv = 1.0f / (float)NBTOT;
    float mean = S * inv;
    float var = Q * inv - mean * mean;
    float r = rsqrtf(var + 1e-5f);
    sc = g[c] * r; sh = be[c] - sc * mean;
}

__global__ void k_stats1(const float* __restrict__ d, int C, float* __restrict__ st2) {
    int c = blockIdx.x, b = blockIdx.y;
    const float4* p4 = (const float4*)(d + (b * C + c) * NN);
    float s = 0.f, sq = 0.f;
    for (int i = threadIdx.x; i < NN / 4; i += 256) {
        float4 v = p4[i];
        s += (v.x + v.y) + (v.z + v.w);
        sq += (v.x * v.x + v.y * v.y) + (v.z * v.z + v.w * v.w);
    }
    __shared__ float shs[8], shq[8];
    for (int o = 16; o; o >>= 1) { s += __shfl_down_sync(~0u, s, o); sq += __shfl_down_sync(~0u, sq, o); }
    if ((threadIdx.x & 31) == 0) { shs[threadIdx.x >> 5] = s; shq[threadIdx.x >> 5] = sq; }
    __syncthreads();
    if (threadIdx.x == 0) {
        float S = 0.f, Q = 0.f;
        #pragma unroll
        for (int i = 0; i < 8; i++) { S += shs[i]; Q += shq[i]; }
        st2[b * 128 + c] = S; st2[b * 128 + 64 + c] = Q;
    }
}

__global__ void k_conv1(const float* __restrict__ x, const float* __restrict__ w,
                        const float* __restrict__ bias, float* __restrict__ y) {
    __shared__ float ws[192], bs[32];
    int t = threadIdx.x;
    if (t < 192) ws[t] = w[t];
    if (t < 32) bs[t] = bias[t];
    __syncthreads();
    int b = blockIdx.y, n = blockIdx.x * 256 + t;
    float in[6];
    #pragma unroll
    for (int c = 0; c < 6; c++) in[c] = x[(b * 6 + c) * NN + n];
    #pragma unroll
    for (int o = 0; o < 32; o++) {
        float a = bs[o];
        #pragma unroll
        for (int c = 0; c < 6; c++) a = fmaf(ws[o * 6 + c], in[c], a);
        y[(b * 32 + o) * NN + n] = a;
    }
}

__global__ void k_bnconv32(const float* __restrict__ yin, const float* __restrict__ st2,
                           const float* __restrict__ g, const float* __restrict__ be,
                           const float* __restrict__ w, const float* __restrict__ bias,
                           float* __restrict__ yout) {
    __shared__ float ws[1024], bs[32], sc[32], sh[32];
    int t = threadIdx.x;
    for (int i = t; i < 1024; i += 256) ws[i] = w[i];
    if (t < 32) { bs[t] = bias[t]; bn_coef8(st2, g, be, t, sc[t], sh[t]); }
    __syncthreads();
    int b = blockIdx.y, n = blockIdx.x * 256 + t;
    float in[32];
    #pragma unroll
    for (int c = 0; c < 32; c++) in[c] = fmaxf(fmaf(sc[c], yin[(b * 32 + c) * NN + n], sh[c]), 0.f);
    for (int o = 0; o < 32; o++) {
        float a = bs[o];
        #pragma unroll
        for (int c = 0; c < 32; c++) a = fmaf(ws[o * 32 + c], in[c], a);
        yout[(b * 32 + o) * NN + n] = a;
    }
}

template<int C>
__global__ void k_bnqkv(const float* __restrict__ yin, const float* __restrict__ st2,
                        const float* __restrict__ g, const float* __restrict__ be,
                        const float* __restrict__ wqk, const float* __restrict__ wv,
                        const float* __restrict__ bv, float* __restrict__ h,
                        hf* __restrict__ qh, hf* __restrict__ ql,
                        hf* __restrict__ vh, hf* __restrict__ vl) {
    __shared__ float wq_s[C*C], wv_s[C*C], bvs[C], sc[C], sh[C];
    int t = threadIdx.x;
    for (int i = t; i < C*C; i += 256) { wq_s[i] = wqk[i]; wv_s[i] = wv[i]; }
    if (t < C) { bvs[t] = bv[t]; bn_coef8(st2, g, be, t, sc[t], sh[t]); }
    __syncthreads();
    int b = blockIdx.y, n = blockIdx.x * 256 + t;
    float in[C];
    #pragma unroll
    for (int c = 0; c < C; c++) {
        float val = fmaxf(fmaf(sc[c], yin[(b * C + c) * NN + n], sh[c]), 0.f);
        in[c] = val;
        h[(b * C + c) * NN + n] = val;
    }
    size_t qoff = ((size_t)b * NN + n) * C;
    for (int og = 0; og < C; og += 4) {
        uint32_t uh[2], ul[2];
        #pragma unroll
        for (int oo = 0; oo < 4; oo += 2) {
            float q0 = 0.f, q1 = 0.f, av0 = bvs[og+oo], av1 = bvs[og+oo+1];
            #pragma unroll
            for (int c = 0; c < C; c++) {
                q0 = fmaf(wq_s[(og+oo) * C + c], in[c], q0);
                q1 = fmaf(wq_s[(og+oo+1) * C + c], in[c], q1);
                av0 = fmaf(wv_s[(og+oo) * C + c], in[c], av0);
                av1 = fmaf(wv_s[(og+oo+1) * C + c], in[c], av1);
            }
            hf h0 = __float2half_rn(q0), h1 = __float2half_rn(q1);
            uh[oo>>1] = ((uint32_t)__half_as_ushort(h1) << 16) | __half_as_ushort(h0);
            ul[oo>>1] = pk2((q0 - __half2float(h0)) * LSC, (q1 - __half2float(h1)) * LSC);
            hf v0 = __float2half_rn(av0), v1 = __float2half_rn(av1);
            vh[(b * C + og+oo) * NN + n] = v0;
            vh[(b * C + og+oo+1) * NN + n] = v1;
            vl[(b * C + og+oo) * NN + n] = __float2half_rn((av0 - __half2float(v0)) * LSC);
            vl[(b * C + og+oo+1) * NN + n] = __float2half_rn((av1 - __half2float(v1)) * LSC);
        }
        *(uint2*)(qh + qoff + og) = make_uint2(uh[0], uh[1]);
        *(uint2*)(ql + qoff + og) = make_uint2(ul[0], ul[1]);
    }
}

// ---- pass A: 128-row tiles, cp.async dbuf B; two 32-col half-passes (64 acc regs) ----
template<int C>
__global__ void __launch_bounds__(256, 2) k_gramA(const hf* __restrict__ qh, const hf* __restrict__ ql,
                                                  float* __restrict__ Mr, float* __restrict__ iLv) {
    constexpr int S = C + 8;
    extern __shared__ float smf[];
    float *RM = smf, *RL = smf + 256;
    hf* Ah = (hf*)(smf + 512);
    hf* Al = Ah + 128 * S;
    hf* Bbase = Al + 128 * S;      // dbuf: each 2*128*S halves
    const int t = threadIdx.x, w = t >> 5, lane = t & 31;
    const int b = blockIdx.y, n0 = blockIdx.x * 128;
    const int rw = (w >> 1) * 32, cw = (w & 1) * 64;
    const int r = lane >> 2, q2 = (lane & 3) * 2;
    const size_t bN = (size_t)b * NN;
    cpa_tile<C, 128, S>(Ah, Al, qh, ql, (bN + n0) * C, t);
    cpa_tile<C, 128, S>(Bbase, Bbase + 128 * S, qh, ql, bN * C, t);
    CPA_COMMIT();
    float Mv[4], Lv[4];
    #pragma unroll
    for (int i = 0; i < 4; i++) { Mv[i] = -1e30f; Lv[i] = 0.f; }
    for (int mt = 0; mt < 32; mt++) {
        CPA_WAIT();
        __syncthreads();
        hf* Bh = Bbase + (mt & 1) * 256 * S;
        hf* Bl = Bh + 128 * S;
        if (mt + 1 < 32) {
            hf* Bn = Bbase + ((mt + 1) & 1) * 256 * S;
            cpa_tile<C, 128, S>(Bn, Bn + 128 * S, qh, ql, (bN + (mt + 1) * 128) * C, t);
            CPA_COMMIT();
        }
        #pragma unroll
        for (int hp = 0; hp < 2; hp++) {
            const int cwh = cw + hp * 32;
            float accH[2][4][4], accX[2][4][4];
            #pragma unroll
            for (int rf = 0; rf < 2; rf++)
                #pragma unroll
                for (int j = 0; j < 4; j++)
                    #pragma unroll
                    for (int e = 0; e < 4; e++) { accH[rf][j][e] = 0.f; accX[rf][j][e] = 0.f; }
            #pragma unroll
            for (int ks = 0; ks < C / 16; ks++) {
                int kb = ks * 16;
                uint32_t ah[2][4], al[2][4];
                #pragma unroll
                for (int rf = 0; rf < 2; rf++) {
                    ldfA(ah[rf], Ah, S, rw + rf * 16, kb, r, q2);
                    ldfA(al[rf], Al, S, rw + rf * 16, kb, r, q2);
                }
                #pragma unroll
                for (int j = 0; j < 4; j++) {
                    int cb = cwh + j * 8;
                    uint32_t bh0 = *(const uint32_t*)(Bh + (cb + r) * S + kb + q2);
                    uint32_t bh1 = *(const uint32_t*)(Bh + (cb + r) * S + kb + q2 + 8);
                    uint32_t bl0 = *(const uint32_t*)(Bl + (cb + r) * S + kb + q2);
                    uint32_t bl1 = *(const uint32_t*)(Bl + (cb + r) * S + kb + q2 + 8);
                    #pragma unroll
                    for (int rf = 0; rf < 2; rf++) {
                        mma16(accH[rf][j], ah[rf], bh0, bh1);
                        mma16(accX[rf][j], ah[rf], bl0, bl1);
                        mma16(accX[rf][j], al[rf], bh0, bh1);
                    }
                }
            }
            #pragma unroll
            for (int rf = 0; rf < 2; rf++)
                #pragma unroll
                for (int h = 0; h < 2; h++) {
                    int i = rf * 2 + h;
                    float sv[8];
                    #pragma unroll
                    for (int j = 0; j < 4; j++) {
                        sv[2*j]   = fmaf(accX[rf][j][2*h],   ILSC, accH[rf][j][2*h]);
                        sv[2*j+1] = fmaf(accX[rf][j][2*h+1], ILSC, accH[rf][j][2*h+1]);
                    }
                    float tm = -1e30f;
                    #pragma unroll
                    for (int j = 0; j < 8; j++) tm = fmaxf(tm, sv[j]);
                    float Mn = fmaxf(Mv[i], tm);
                    float l = Lv[i] * __expf(Mv[i] - Mn);
                    #pragma unroll
                    for (int j = 0; j < 8; j++) l += __expf(sv[j] - Mn);
                    Mv[i] = Mn; Lv[i] = l;
                }
        }
        __syncthreads();
    }
    #pragma unroll
    for (int i = 0; i < 4; i++)
        #pragma unroll
        for (int o = 1; o <= 2; o <<= 1) {
            float M2 = __shfl_xor_sync(~0u, Mv[i], o);
            float L2 = __shfl_xor_sync(~0u, Lv[i], o);
            float Mn = fmaxf(Mv[i], M2);
            Lv[i] = Lv[i] * __expf(Mv[i] - Mn) + L2 * __expf(M2 - Mn);
            Mv[i] = Mn;
        }
    __syncthreads();
    if ((lane & 3) == 0) {
        #pragma unroll
        for (int i = 0; i < 4; i++) {
            int row = rw + (i >> 1) * 16 + (i & 1) * 8 + r;
            RM[row * 2 + (w & 1)] = Mv[i];
            RL[row * 2 + (w & 1)] = Lv[i];
        }
    }
    __syncthreads();
    if (t < 128) {
        float M0 = RM[t*2], M1 = RM[t*2+1], L0 = RL[t*2], L1 = RL[t*2+1];
        float Mn = fmaxf(M0, M1);
        float L = L0 * __expf(M0 - Mn) + L1 * __expf(M1 - Mn);
        Mr[b * NN + n0 + t] = Mn;
        iLv[b * NN + n0 + t] = 1.0f / L;
    }
}

// ---- pass B: 128 m-rows, cp.async dbuf Qn/V/M/L; E hi+lo; xr = E x V ----
template<int C>
__global__ void __launch_bounds__(256) k_gramB(const hf* __restrict__ qh, const hf* __restrict__ ql,
                                               const hf* __restrict__ vhp, const hf* __restrict__ vlp,
                                               const float* __restrict__ Mr, const float* __restrict__ iLv,
                                               float* __restrict__ xrT) {
    constexpr int S = C + 8, SE = 72, NJ2 = C / 16;
    extern __shared__ float smf[];
    float *MshB = smf;
    float *LshB = smf + 128;
    float *Red  = smf + 256;
    float *Sinv = smf + 512;
    hf* Qmh = (hf*)(smf + 640);
    hf* Qml = Qmh + 128 * S;
    hf* Qbase = Qml + 128 * S;
    hf* Vbase = Qbase + 2 * 128 * S;
    hf* Eh = Vbase + 2 * 2 * C * SE;
    hf* El = Eh + 128 * SE;
    const int t = threadIdx.x, w = t >> 5, lane = t & 31;
    const int b = blockIdx.y, m0 = blockIdx.x * 128;
    const int rw = (w >> 1) * 32, cw = (w & 1) * 32, cw2 = (w & 1) * (C / 2);
    const int r = lane >> 2, q2 = (lane & 3) * 2;
    const size_t bN = (size_t)b * NN, bC = (size_t)b * C;
    cpa_tile<C, 128, S>(Qmh, Qml, qh, ql, (bN + m0) * C, t);
    cpa_tile<C, 64, S>(Qbase, Qbase + 64 * S, qh, ql, bN * C, t);
    cpa_vtile<C, SE>(Vbase, Vbase + C * SE, vhp, vlp, bC, 0, t);
    if (t < 16) cpa16(MshB + t * 4, Mr + bN + t * 4);
    else if (t < 32) cpa16(LshB + (t - 16) * 4, iLv + bN + (t - 16) * 4);
    CPA_COMMIT();
    float acc2H[2][NJ2][4], acc2X[2][NJ2][4];
    #pragma unroll
    for (int rf = 0; rf < 2; rf++)
        #pragma unroll
        for (int j = 0; j < NJ2; j++)
            #pragma unroll
            for (int e = 0; e < 4; e++) { acc2H[rf][j][e] = 0.f; acc2X[rf][j][e] = 0.f; }
    float sacc[4] = {0.f, 0.f, 0.f, 0.f};
    for (int nt = 0; nt < 64; nt++) {
        CPA_WAIT();
        __syncthreads();
        int bi = nt & 1;
        hf* Qnh = Qbase + bi * 128 * S;
        hf* Qnl = Qnh + 64 * S;
        hf* Vh = Vbase + bi * 2 * C * SE;
        hf* Vl = Vh + C * SE;
        const float* Msh = MshB + bi * 64;
        const float* Lsh = LshB + bi * 64;
        if (nt + 1 < 64) {
            int bj = (nt + 1) & 1, n1 = (nt + 1) * 64;
            hf* Qn2 = Qbase + bj * 128 * S;
            hf* V2 = Vbase + bj * 2 * C * SE;
            cpa_tile<C, 64, S>(Qn2, Qn2 + 64 * S, qh, ql, (bN + n1) * C, t);
            cpa_vtile<C, SE>(V2, V2 + C * SE, vhp, vlp, bC, n1, t);
            if (t < 16) cpa16(MshB + bj * 64 + t * 4, Mr + bN + n1 + t * 4);
            else if (t < 32) cpa16(LshB + bj * 64 + (t - 16) * 4, iLv + bN + n1 + (t - 16) * 4);
            CPA_COMMIT();
        }
        float accS[2][4][4], accSX[2][4][4];
        #pragma unroll
        for (int rf = 0; rf < 2; rf++)
            #pragma unroll
            for (int j = 0; j < 4; j++)
                #pragma unroll
                for (int e = 0; e < 4; e++) { accS[rf][j][e] = 0.f; accSX[rf][j][e] = 0.f; }
        #pragma unroll
        for (int ks = 0; ks < C / 16; ks++) {
            int kb = ks * 16;
            uint32_t ah[2][4], al[2][4];
            #pragma unroll
            for (int rf = 0; rf < 2; rf++) {
                ldfA(ah[rf], Qmh, S, rw + rf * 16, kb, r, q2);
                ldfA(al[rf], Qml, S, rw + rf * 16, kb, r, q2);
            }
            #pragma unroll
            for (int j = 0; j < 4; j++) {
                int cb = cw + j * 8;
                uint32_t bh0 = *(const uint32_t*)(Qnh + (cb + r) * S + kb + q2);
                uint32_t bh1 = *(const uint32_t*)(Qnh + (cb + r) * S + kb + q2 + 8);
                uint32_t bl0 = *(const uint32_t*)(Qnl + (cb + r) * S + kb + q2);
                uint32_t bl1 = *(const uint32_t*)(Qnl + (cb + r) * S + kb + q2 + 8);
                #pragma unroll
                for (int rf = 0; rf < 2; rf++) {
                    mma16(accS[rf][j], ah[rf], bh0, bh1);
                    mma16(accSX[rf][j], ah[rf], bl0, bl1);
                    mma16(accSX[rf][j], al[rf], bh0, bh1);
                }
            }
        }
        #pragma unroll
        for (int rf = 0; rf < 2; rf++)
            #pragma unroll
            for (int h = 0; h < 2; h++) {
                int row = rw + rf * 16 + h * 8 + r;
                #pragma unroll
                for (int j = 0; j < 4; j++) {
                    int col = cw + j * 8 + q2;
                    float s0 = fmaf(accSX[rf][j][2*h],   ILSC, accS[rf][j][2*h]);
                    float s1 = fmaf(accSX[rf][j][2*h+1], ILSC, accS[rf][j][2*h+1]);
                    float e0 = __expf(s0 - Msh[col])     * Lsh[col];
                    float e1 = __expf(s1 - Msh[col + 1]) * Lsh[col + 1];
                    sacc[rf * 2 + h] += e0 + e1;
                    hf eh0 = __float2half_rn(e0), eh1 = __float2half_rn(e1);
                    *(uint32_t*)(Eh + row * SE + col) =
                        ((uint32_t)__half_as_ushort(eh1) << 16) | __half_as_ushort(eh0);
                    *(uint32_t*)(El + row * SE + col) =
                        pk2((e0 - __half2float(eh0)) * LSC, (e1 - __half2float(eh1)) * LSC);
                }
            }
        __syncthreads();
        #pragma unroll
        for (int ks = 0; ks < 4; ks++) {
            int kb = ks * 16;
            uint32_t ef[2][4], efl[2][4];
            #pragma unroll
            for (int rf = 0; rf < 2; rf++) {
                ldfA(ef[rf], Eh, SE, rw + rf * 16, kb, r, q2);
                ldfA(efl[rf], El, SE, rw + rf * 16, kb, r, q2);
            }
            #pragma unroll
            for (int j = 0; j < NJ2; j++) {
                int cc = cw2 + j * 8;
                uint32_t bh0 = *(const uint32_t*)(Vh + (cc + r) * SE + kb + q2);
                uint32_t bh1 = *(const uint32_t*)(Vh + (cc + r) * SE + kb + q2 + 8);
                uint32_t bl0 = *(const uint32_t*)(Vl + (cc + r) * SE + kb + q2);
                uint32_t bl1 = *(const uint32_t*)(Vl + (cc + r) * SE + kb + q2 + 8);
                #pragma unroll
                for (int rf = 0; rf < 2; rf++) {
                    mma16(acc2H[rf][j], ef[rf], bh0, bh1);
                    mma16(acc2X[rf][j], ef[rf], bl0, bl1);
                    mma16(acc2X[rf][j], efl[rf], bh0, bh1);
                }
            }
        }
    }
    #pragma unroll
    for (int i = 0; i < 4; i++) {
        sacc[i] += __shfl_xor_sync(~0u, sacc[i], 1);
        sacc[i] += __shfl_xor_sync(~0u, sacc[i], 2);
    }
    __syncthreads();
    if ((lane & 3) == 0) {
        #pragma unroll
        for (int i = 0; i < 4; i++) {
            int row = rw + (i >> 1) * 16 + (i & 1) * 8 + r;
            Red[row * 2 + (w & 1)] = sacc[i];
        }
    }
    __syncthreads();
    if (t < 128) Sinv[t] = 1.0f / (1e-9f + Red[t*2] + Red[t*2+1]);
    __syncthreads();
    #pragma unroll
    for (int rf = 0; rf < 2; rf++)
        #pragma unroll
        for (int h = 0; h < 2; h++) {
            int row = rw + rf * 16 + h * 8 + r;
            float si = Sinv[row];
            float* dst = xrT + (bN + m0 + row) * C;
            #pragma unroll
            for (int j = 0; j < NJ2; j++) {
                int col = cw2 + j * 8 + q2;
                float u0 = fmaf(acc2X[rf][j][2*h],   ILSC, acc2H[rf][j][2*h]);
                float u1 = fmaf(acc2X[rf][j][2*h+1], ILSC, acc2H[rf][j][2*h+1]);
                *(float2*)(dst + col) = make_float2(u0 * si, u1 * si);
            }
        }
}

template<int C>
__global__ void k_diffconv(const float* __restrict__ h, const float* __restrict__ xrT,
                           const float* __restrict__ wt, const float* __restrict__ bt,
                           float* __restrict__ tp) {
    __shared__ float ws[C*C], bs[C];
    int t = threadIdx.x;
    for (int i = t; i < C*C; i += 256) ws[i] = wt[i];
    if (t < C) bs[t] = bt[t];
    __syncthreads();
    int b = blockIdx.y, n = blockIdx.x * 256 + t;
    const float* xs = xrT + ((size_t)b * NN + n) * C;
    float din[C];
    #pragma unroll
    for (int c = 0; c < C; c += 4) {
        float4 xv = *(const float4*)(xs + c);
        din[c]     = h[(b * C + c) * NN + n]     - xv.x;
        din[c + 1] = h[(b * C + c + 1) * NN + n] - xv.y;
        din[c + 2] = h[(b * C + c + 2) * NN + n] - xv.z;
        din[c + 3] = h[(b * C + c + 3) * NN + n] - xv.w;
    }
    for (int o = 0; o < C; o++) {
        float a = bs[o];
        #pragma unroll
        for (int c = 0; c < C; c++) a = fmaf(ws[o * C + c], din[c], a);
        tp[(b * C + o) * NN + n] = a;
    }
}

template<int C>
__global__ void k_resid(const float* __restrict__ h, const float* __restrict__ tp,
                        const float* __restrict__ st2, const float* __restrict__ g,
                        const float* __restrict__ be, float* __restrict__ out) {
    __shared__ float scs, shs;
    int idx = blockIdx.x * 256 + threadIdx.x;
    int c = (idx >> 12) & (C - 1);
    if (threadIdx.x == 0) bn_coef8(st2, g, be, c, scs, shs);
    __syncthreads();
    out[idx] = h[idx] + fmaxf(fmaf(scs, tp[idx], shs), 0.f);
}

__global__ void k_max(const float* __restrict__ d, float* __restrict__ gf) {
    int bc = blockIdx.x;
    const float* p = d + bc * NN;
    float m = -1e30f;
    for (int i = threadIdx.x; i < NN; i += 256) m = fmaxf(m, p[i]);
    __shared__ float sm_[8];
    for (int o = 16; o; o >>= 1) m = fmaxf(m, __shfl_down_sync(~0u, m, o));
    if ((threadIdx.x & 31) == 0) sm_[threadIdx.x >> 5] = m;
    __syncthreads();
    if (threadIdx.x == 0) {
        float M = sm_[0];
        #pragma unroll
        for (int i = 1; i < 8; i++) M = fmaxf(M, sm_[i]);
        gf[bc] = M;
    }
}

__global__ void k_concatconv(const float* __restrict__ h3, const float* __restrict__ gf1,
                             const float* __restrict__ w3, const float* __restrict__ b3,
                             float* __restrict__ y3) {
    __shared__ float ws[4096], K[64];
    int t = threadIdx.x, b = blockIdx.y;
    for (int i = t; i < 4096; i += 256) ws[i] = w3[i];
    __syncthreads();
    if (t < 64) {
        float a = b3[t];
        #pragma unroll
        for (int c = 0; c < 32; c++) a = fmaf(ws[t * 64 + 32 + c], gf1[b * 32 + c], a);
        K[t] = a;
    }
    __syncthreads();
    int n = blockIdx.x * 256 + t;
    float in[32];
    #pragma unroll
    for (int c = 0; c < 32; c++) in[c] = h3[(b * 32 + c) * NN + n];
    for (int o = 0; o < 64; o++) {
        float a = K[o];
        #pragma unroll
        for (int c = 0; c < 32; c++) a = fmaf(ws[o * 64 + c], in[c], a);
        y3[(b * 64 + o) * NN + n] = a;
    }
}

extern "C" void kernel_launch(void* const* d_in, const int* in_sizes, int n_in,
                              void* d_out, int out_size) {
    const float *x = (const float*)d_in[0], *w1 = (const float*)d_in[1], *b1 = (const float*)d_in[2],
        *g1 = (const float*)d_in[3], *be1 = (const float*)d_in[4], *w2 = (const float*)d_in[5],
        *b2 = (const float*)d_in[6], *g2 = (const float*)d_in[7], *be2 = (const float*)d_in[8],
        *a1_wqk = (const float*)d_in[9], *a1_wv = (const float*)d_in[10], *a1_bv = (const float*)d_in[11],
        *a1_wt = (const float*)d_in[12], *a1_bt = (const float*)d_in[13], *a1_g = (const float*)d_in[14],
        *a1_b = (const float*)d_in[15], *w3 = (const float*)d_in[16], *b3 = (const float*)d_in[17],
        *g3 = (const float*)d_in[18], *be3 = (const float*)d_in[19], *a2_wqk = (const float*)d_in[20],
        *a2_wv = (const float*)d_in[21], *a2_bv = (const float*)d_in[22], *a2_wt = (const float*)d_in[23],
        *a2_bt = (const float*)d_in[24], *a2_g = (const float*)d_in[25], *a2_b = (const float*)d_in[26];

    float* S = nullptr;
    cudaGetSymbolAddress((void**)&S, SCR);
    float *y1 = S, *y2 = S + BUF, *h2 = S + 2*BUF, *qkB = S + 3*BUF, *vB = S + 4*BUF,
          *xrT = S + 5*BUF, *tpb = S + 6*BUF, *h3 = S + 7*BUF;
    float *Mr = S + 8*BUF, *iL = Mr + BB*NN, *gf1 = iL + BB*NN, *st2 = gf1 + 256 + 5*128;
    hf *qh = (hf*)qkB, *ql = qh + (size_t)BB*NN*64;
    hf *vh = (hf*)vB, *vl = vh + (size_t)BB*NN*64;
    float* outh = (float*)d_out;
    float* outgf = outh + BB * 64 * NN;

    int smA32 = 2048 + (2*128*40 + 4*128*40) * 2;
    int smA64 = 2048 + (2*128*72 + 4*128*72) * 2;
    int smB32 = 2560 + (2*128*40 + 4*64*40 + 4*32*72 + 2*128*72) * 2;
    int smB64 = 2560 + (2*128*72 + 4*64*72 + 4*64*72 + 2*128*72) * 2;
    cudaFuncSetAttribute(k_gramA<32>, cudaFuncAttributeMaxDynamicSharedMemorySize, smA32);
    cudaFuncSetAttribute(k_gramA<64>, cudaFuncAttributeMaxDynamicSharedMemorySize, smA64);
    cudaFuncSetAttribute(k_gramB<32>, cudaFuncAttributeMaxDynamicSharedMemorySize, smB32);
    cudaFuncSetAttribute(k_gramB<64>, cudaFuncAttributeMaxDynamicSharedMemorySize, smB64);

    dim3 gN(NN / 256, BB), gA(32, BB);
    k_conv1<<<gN, 256>>>(x, w1, b1, y1);
    k_stats1<<<dim3(32, BB), 256>>>(y1, 32, st2);
    k_bnconv32<<<gN, 256>>>(y1, st2, g1, be1, w2, b2, y2);
    k_stats1<<<dim3(32, BB), 256>>>(y2, 32, st2);
    k_bnqkv<32><<<gN, 256>>>(y2, st2, g2, be2, a1_wqk, a1_wv, a1_bv, h2, qh, ql, vh, vl);
    k_gramA<32><<<gA, 256, smA32>>>(qh, ql, Mr, iL);
    k_gramB<32><<<gA, 256, smB32>>>(qh, ql, vh, vl, Mr, iL, xrT);
    k_diffconv<32><<<gN, 256>>>(h2, xrT, a1_wt, a1_bt, tpb);
    k_stats1<<<dim3(32, BB), 256>>>(tpb, 32, st2);
    k_resid<32><<<BB*32*NN/256, 256>>>(h2, tpb, st2, a1_g, a1_b, h3);
    k_max<<<BB * 32, 256>>>(h3, gf1);
    k_concatconv<<<gN, 256>>>(h3, gf1, w3, b3, y2);
    k_stats1<<<dim3(64, BB), 256>>>(y2, 64, st2);
    k_bnqkv<64><<<gN, 256>>>(y2, st2, g3, be3, a2_wqk, a2_wv, a2_bv, y1, qh, ql, vh, vl);
    k_gramA<64><<<gA, 256, smA64>>>(qh, ql, Mr, iL);
    k_gramB<64><<<gA, 256, smB64>>>(qh, ql, vh, vl, Mr, iL, xrT);
    k_diffconv<64><<<gN, 256>>>(y1, xrT, a2_wt, a2_bt, tpb);
    k_stats1<<<dim3(64, BB), 256>>>(tpb, 64, st2);
    k_resid<64><<<BB*64*NN/256, 256>>>(y1, tpb, st2, a2_g, a2_b, outh);
    k_max<<<BB * 64, 256>>>(outh, outgf);
}